// round 5
// baseline (speedup 1.0000x reference)
#include <cuda_runtime.h>
#include <cstdint>

#define GROUPS  2048
#define MM      64
#define CC      128
#define TOK     8192
#define RK      8
#define RRR     512
#define MASKN   524288

__device__ float g_s [(size_t)GROUPS * TOK];  // 64 MB group sums
__device__ float g_t1[(size_t)GROUPS * RRR];  // 4 MB
__device__ float g_u2[(size_t)GROUPS * RRR];  // 4 MB
__device__ float g_w4[RRR * RRR];             // 1 MB folded operator
__device__ int   g_flags[2];                  // [ge2, odd] — memset to 0 each launch

// ---------------------------------------------------------------------------
// Mask dtype scan: 64 blocks, OR-reduce byte patterns into g_flags.
// ---------------------------------------------------------------------------
__global__ void __launch_bounds__(256) k0_scan_mask(const unsigned char* __restrict__ mask)
{
    const uint4* p = (const uint4*)mask;
    unsigned acc = 0;
    int i = blockIdx.x * 256 + threadIdx.x;
    const int stride = 64 * 256;
    for (; i < MASKN / 16; i += stride) {
        uint4 v = p[i];
        acc |= (v.x | v.y | v.z | v.w);
    }
    // warp+block reduce via ballot-free OR in smem
    __shared__ unsigned sacc;
    if (threadIdx.x == 0) sacc = 0;
    __syncthreads();
    #pragma unroll
    for (int off = 16; off >= 1; off >>= 1)
        acc |= __shfl_xor_sync(0xffffffffu, acc, off);
    if ((threadIdx.x & 31) == 0) atomicOr(&sacc, acc);
    __syncthreads();
    if (threadIdx.x == 0) {
        unsigned a = sacc;
        if (a & 0xFEFEFEFEu) atomicOr(&g_flags[0], 1);  // byte >= 2 -> float32
        if (a & 0xFFFFFF00u) atomicOr(&g_flags[1], 1);  // off-word byte -> uint8
    }
}

// ---------------------------------------------------------------------------
// Fold: W4[(o,p,C),(a,d,F)] from core and the 4 small factors. 64 blocks.
// ---------------------------------------------------------------------------
__global__ void __launch_bounds__(256) fold_w4(
    const float* __restrict__ core,
    const float* __restrict__ of0, const float* __restrict__ of1,
    const float* __restrict__ if0, const float* __restrict__ if1)
{
    __shared__ float bufA[4096], bufB[4096];
    __shared__ float sf[4][64];
    const int tid = threadIdx.x;
    const int C = blockIdx.x >> 3, F = blockIdx.x & 7;

    if (tid < 64)       sf[0][tid]       = of0[tid];
    else if (tid < 128) sf[1][tid - 64]  = of1[tid - 64];
    else if (tid < 192) sf[2][tid - 128] = if0[tid - 128];
    else                sf[3][tid - 192] = if1[tid - 192];

    #pragma unroll
    for (int i = tid; i < 4096; i += 256) {
        int A = i >> 9, B = (i >> 6) & 7, D = (i >> 3) & 7, E = i & 7;
        bufA[i] = core[A * 32768 + B * 4096 + C * 512 + D * 64 + E * 8 + F];
    }
    __syncthreads();
    #pragma unroll
    for (int i = tid; i < 4096; i += 256) {   // M1[A,B,D,d] = sum_E K * if1[d,E]
        int ABD = i >> 3, d = i & 7;
        float acc = 0.f;
        #pragma unroll
        for (int E = 0; E < 8; E++) acc += bufA[ABD * 8 + E] * sf[3][d * 8 + E];
        bufB[i] = acc;
    }
    __syncthreads();
    #pragma unroll
    for (int i = tid; i < 4096; i += 256) {   // M2[A,B,d,a] = sum_D M1 * if0[a,D]
        int AB = i >> 6, d = (i >> 3) & 7, a = i & 7;
        float acc = 0.f;
        #pragma unroll
        for (int D = 0; D < 8; D++) acc += bufB[(AB * 8 + D) * 8 + d] * sf[2][a * 8 + D];
        bufA[i] = acc;
    }
    __syncthreads();
    #pragma unroll
    for (int i = tid; i < 4096; i += 256) {   // M3[B,d,a,o] = sum_A M2 * of0[o,A]
        int B = i >> 9, d = (i >> 6) & 7, a = (i >> 3) & 7, o = i & 7;
        float acc = 0.f;
        #pragma unroll
        for (int A = 0; A < 8; A++)
            acc += bufA[((A * 8 + B) * 8 + d) * 8 + a] * sf[0][o * 8 + A];
        bufB[i] = acc;
    }
    __syncthreads();
    #pragma unroll
    for (int i = tid; i < 4096; i += 256) {   // W4 = sum_B M3 * of1[p,B]
        int o = i >> 9, p = (i >> 6) & 7, a = (i >> 3) & 7, d = i & 7;
        float acc = 0.f;
        #pragma unroll
        for (int B = 0; B < 8; B++)
            acc += bufB[((B * 8 + d) * 8 + a) * 8 + o] * sf[1][p * 8 + B];
        g_w4[(size_t)((o * 8 + p) * 8 + C) * RRR + a * 64 + d * 8 + F] = acc;
    }
}

// ---------------------------------------------------------------------------
// Kernel 1: grid 4096 (2 blocks per group, 32 m-cells each).
// s = sum of 4 tokens -> scratch; T1[m,F] = sum_e s[m,e]*in_f2[e,F].
// ---------------------------------------------------------------------------
__global__ void __launch_bounds__(256) k1_reduce_project(
    const float* __restrict__ x,
    const float* __restrict__ in_f2)   // (128,8)
{
    __shared__ float s[32 * 129];
    __shared__ float f2s[CC * RK];

    const int tid = threadIdx.x;
    const int g = blockIdx.x >> 1, h = blockIdx.x & 1;
    const size_t base = (size_t)g * (4 * TOK) + h * 4096;

    #pragma unroll
    for (int i = tid; i < CC * RK; i += 256) f2s[i] = in_f2[i];

    const float4* xb = (const float4*)(x + base);
    float4*       sg = (float4*)(g_s + (size_t)g * TOK + h * 4096);
    #pragma unroll
    for (int it = 0; it < 4; it++) {
        int i = tid + it * 256;               // float4 index in half-group [0,1024)
        float4 v0 = xb[i];
        float4 v1 = xb[i + 2048];
        float4 v2 = xb[i + 4096];
        float4 v3 = xb[i + 6144];
        float4 r;
        r.x = (v0.x + v1.x) + (v2.x + v3.x);
        r.y = (v0.y + v1.y) + (v2.y + v3.y);
        r.z = (v0.z + v1.z) + (v2.z + v3.z);
        r.w = (v0.w + v1.w) + (v2.w + v3.w);
        sg[i] = r;
        int m = i >> 5;                       // local m 0..31
        int e = (i & 31) << 2;
        float* sp = &s[m * 129 + e];
        sp[0] = r.x; sp[1] = r.y; sp[2] = r.z; sp[3] = r.w;
    }
    __syncthreads();

    // one (m,F) per thread: 32 m x 8 F = 256
    {
        int m = tid & 31;
        int F = tid >> 5;
        float acc = 0.f;
        const float* srow = &s[m * 129];
        #pragma unroll 8
        for (int e = 0; e < CC; e++)
            acc += srow[e] * f2s[e * RK + F];
        g_t1[(size_t)g * RRR + (h * 32 + m) * 8 + F] = acc;
    }
}

// ---------------------------------------------------------------------------
// Kernel 2: U2 = T1 @ W4^T.  BM=128 BN=64 BK=16, 256 thr, 8x4 tile, f32x2.
// grid = (16, 8) = 128 blocks.
// ---------------------------------------------------------------------------
__global__ void __launch_bounds__(256) k2_core_gemm()
{
    __shared__ __align__(16) float As[16][132];
    __shared__ __align__(16) float Bs[16][68];

    const int tid = threadIdx.x;
    const int bm = blockIdx.x * 128;
    const int bn = blockIdx.y * 64;
    const int tx = tid & 15;           // 16 cols of 4 -> n
    const int ty = tid >> 4;           // 16 rows of 8 -> m
    const int lr = tid >> 2;           // 0..63 load row
    const int lk = (tid & 3) << 2;     // k offset 0,4,8,12

    unsigned long long acc[8][2];
    #pragma unroll
    for (int i = 0; i < 8; i++) { acc[i][0] = 0ULL; acc[i][1] = 0ULL; }

    for (int k0 = 0; k0 < RRR; k0 += 16) {
        float4 a0 = *(const float4*)(g_t1 + (size_t)(bm + lr)      * RRR + k0 + lk);
        float4 a1 = *(const float4*)(g_t1 + (size_t)(bm + 64 + lr) * RRR + k0 + lk);
        float4 b0 = *(const float4*)(g_w4 + (size_t)(bn + lr)      * RRR + k0 + lk);
        __syncthreads();
        As[lk + 0][lr] = a0.x; As[lk + 1][lr] = a0.y;
        As[lk + 2][lr] = a0.z; As[lk + 3][lr] = a0.w;
        As[lk + 0][64 + lr] = a1.x; As[lk + 1][64 + lr] = a1.y;
        As[lk + 2][64 + lr] = a1.z; As[lk + 3][64 + lr] = a1.w;
        Bs[lk + 0][lr] = b0.x; Bs[lk + 1][lr] = b0.y;
        Bs[lk + 2][lr] = b0.z; Bs[lk + 3][lr] = b0.w;
        __syncthreads();
        #pragma unroll
        for (int k = 0; k < 16; k++) {
            float4 av0 = *(const float4*)&As[k][ty * 8];
            float4 av1 = *(const float4*)&As[k][ty * 8 + 4];
            unsigned long long bv0 = *(const unsigned long long*)&Bs[k][tx * 4];
            unsigned long long bv1 = *(const unsigned long long*)&Bs[k][tx * 4 + 2];
            float a[8] = {av0.x, av0.y, av0.z, av0.w, av1.x, av1.y, av1.z, av1.w};
            #pragma unroll
            for (int i = 0; i < 8; i++) {
                unsigned long long ap;
                asm("mov.b64 %0, {%1, %1};" : "=l"(ap) : "f"(a[i]));
                asm("fma.rn.f32x2 %0, %1, %2, %0;" : "+l"(acc[i][0]) : "l"(ap), "l"(bv0));
                asm("fma.rn.f32x2 %0, %1, %2, %0;" : "+l"(acc[i][1]) : "l"(ap), "l"(bv1));
            }
        }
    }
    #pragma unroll
    for (int i = 0; i < 8; i++) {
        size_t row = (size_t)(bm + ty * 8 + i) * RRR + bn + tx * 4;
        *(unsigned long long*)&g_u2[row]     = acc[i][0];
        *(unsigned long long*)&g_u2[row + 2] = acc[i][1];
    }
}

// ---------------------------------------------------------------------------
// Kernel 3: grid 4096 (2 blocks per group). out = (u2·f2^T + s) * invw.
// ---------------------------------------------------------------------------
__global__ void __launch_bounds__(256) k3_stream(
    const float* __restrict__ out_f2,
    const void*  __restrict__ maskp,
    float* __restrict__ out)
{
    __shared__ float f2t[RK * CC];   // f2t[C*128+q]
    __shared__ float u2s[256];       // half-group u2
    __shared__ float invw[32];

    const int tid = threadIdx.x;
    const int g = blockIdx.x >> 1, h = blockIdx.x & 1;

    if (tid < 64)
        ((float4*)u2s)[tid] = ((const float4*)(g_u2 + (size_t)g * RRR + h * 256))[tid];
    #pragma unroll
    for (int i = tid; i < RK * CC; i += 256) {
        int q = i >> 3, Cr = i & 7;
        f2t[Cr * CC + q] = out_f2[i];
    }
    if (tid < 32) {
        int ge2 = g_flags[0], odd = g_flags[1];
        int m = h * 32 + tid;
        int w;
        if (ge2) {            // float32 mask
            const float* mf = (const float*)maskp + (size_t)g * 256;
            w = (mf[m] != 0.f ? 0 : 1) + (mf[m + 64] != 0.f ? 0 : 1)
              + (mf[m + 128] != 0.f ? 0 : 1) + (mf[m + 192] != 0.f ? 0 : 1);
        } else if (odd) {     // uint8 mask
            const unsigned char* mb = (const unsigned char*)maskp + (size_t)g * 256;
            w = (mb[m] ? 0 : 1) + (mb[m + 64] ? 0 : 1)
              + (mb[m + 128] ? 0 : 1) + (mb[m + 192] ? 0 : 1);
        } else {              // int32 mask
            const int* mi = (const int*)maskp + (size_t)g * 256;
            w = (mi[m] ? 0 : 1) + (mi[m + 64] ? 0 : 1)
              + (mi[m + 128] ? 0 : 1) + (mi[m + 192] ? 0 : 1);
        }
        invw[tid] = (w > 0) ? 1.0f / ((float)w + 1e-10f) : 0.0f;
    }
    __syncthreads();

    const float4* sg = (const float4*)(g_s + (size_t)g * TOK + h * 4096);
    float4*       og = (float4*)(out + (size_t)g * TOK + h * 4096);
    #pragma unroll
    for (int it = 0; it < 4; it++) {
        int i  = tid + it * 256;          // float4 idx in half-group [0,1024)
        int m  = i >> 5;                  // local m 0..31
        int q0 = (i & 31) << 2;
        float4 sv = sg[i];
        float r0 = 0.f, r1 = 0.f, r2 = 0.f, r3 = 0.f;
        #pragma unroll
        for (int Cr = 0; Cr < 8; Cr++) {
            float u = u2s[m * 8 + Cr];
            float4 f = *(const float4*)&f2t[Cr * CC + q0];
            r0 += u * f.x; r1 += u * f.y; r2 += u * f.z; r3 += u * f.w;
        }
        float iw = invw[m];
        float4 ov;
        ov.x = (r0 + sv.x) * iw;
        ov.y = (r1 + sv.y) * iw;
        ov.z = (r2 + sv.z) * iw;
        ov.w = (r3 + sv.w) * iw;
        og[i] = ov;
    }
}

// ---------------------------------------------------------------------------
// inputs: 0:x 1:core 2:out_f0 3:out_f1 4:out_f2 5:in_f0 6:in_f1 7:in_f2 8:mask
// ---------------------------------------------------------------------------
extern "C" void kernel_launch(void* const* d_in, const int* in_sizes, int n_in,
                              void* d_out, int out_size)
{
    const float* x      = (const float*)d_in[0];
    const float* core   = (const float*)d_in[1];
    const float* out_f0 = (const float*)d_in[2];
    const float* out_f1 = (const float*)d_in[3];
    const float* out_f2 = (const float*)d_in[4];
    const float* in_f0  = (const float*)d_in[5];
    const float* in_f1  = (const float*)d_in[6];
    const float* in_f2  = (const float*)d_in[7];
    float* out = (float*)d_out;

    void* flags_ptr = nullptr;
    cudaGetSymbolAddress(&flags_ptr, g_flags);
    cudaMemsetAsync(flags_ptr, 0, 2 * sizeof(int));

    k0_scan_mask<<<64, 256>>>((const unsigned char*)d_in[8]);
    fold_w4<<<64, 256>>>(core, out_f0, out_f1, in_f0, in_f1);
    k1_reduce_project<<<2 * GROUPS, 256>>>(x, in_f2);
    dim3 g2(GROUPS / 128, RRR / 64);
    k2_core_gemm<<<g2, 256>>>();
    k3_stream<<<2 * GROUPS, 256>>>(out_f2, d_in[8], out);
}